// round 7
// baseline (speedup 1.0000x reference)
#include <cuda_runtime.h>
#include <cuda_bf16.h>
#include <cstdint>

#define N_NODES 100000
#define N_EDGES 1600000
#define FEAT 128
#define NCLS 47
#define SCAN_BLK 1024
#define N_SCAN_BLKS ((N_NODES + SCAN_BLK - 1) / SCAN_BLK)   // 98

// ---------------- scratch (no allocation allowed) ----------------
__device__ __align__(16) float g_h0[N_NODES * FEAT];
__device__ __align__(16) float g_h1[N_NODES * FEAT];
__device__ __align__(16) float g_mean[N_NODES * FEAT];
__device__ __align__(16) __nv_bfloat16 g_hb0[N_NODES * FEAT];
__device__ __align__(16) __nv_bfloat16 g_hb1[N_NODES * FEAT];
__device__ __align__(16) int   g_cnt[N_NODES];
__device__ __align__(16) int   g_off[N_NODES + 1];
__device__ __align__(16) int   g_cur[N_NODES];
__device__ __align__(16) int   g_esrc[N_EDGES];
__device__ __align__(16) int   g_blksum[N_SCAN_BLKS];

// ---------------- PTX helpers ----------------
__device__ __forceinline__ uint32_t smem_u32(const void* p) {
    uint32_t a;
    asm("{ .reg .u64 t; cvta.to.shared.u64 t, %1; cvt.u32.u64 %0, t; }"
        : "=r"(a) : "l"(p));
    return a;
}
__device__ __forceinline__ void ldsm4(uint32_t* r, uint32_t a) {
    asm volatile("ldmatrix.sync.aligned.m8n8.x4.shared.b16 {%0,%1,%2,%3}, [%4];"
                 : "=r"(r[0]), "=r"(r[1]), "=r"(r[2]), "=r"(r[3]) : "r"(a));
}
__device__ __forceinline__ void ldsm4t(uint32_t* r, uint32_t a) {
    asm volatile("ldmatrix.sync.aligned.m8n8.x4.trans.shared.b16 {%0,%1,%2,%3}, [%4];"
                 : "=r"(r[0]), "=r"(r[1]), "=r"(r[2]), "=r"(r[3]) : "r"(a));
}
__device__ __forceinline__ void mma_bf16(float* d, const uint32_t* a, const uint32_t* b) {
    asm volatile(
        "mma.sync.aligned.m16n8k16.row.col.f32.bf16.bf16.f32 "
        "{%0,%1,%2,%3}, {%4,%5,%6,%7}, {%8,%9}, {%0,%1,%2,%3};"
        : "+f"(d[0]), "+f"(d[1]), "+f"(d[2]), "+f"(d[3])
        : "r"(a[0]), "r"(a[1]), "r"(a[2]), "r"(a[3]), "r"(b[0]), "r"(b[1]));
}
__device__ __forceinline__ void split_bf(float x, __nv_bfloat16& hi, __nv_bfloat16& lo) {
    hi = __float2bfloat16_rn(x);
    lo = __float2bfloat16_rn(x - __bfloat162float(hi));
}
__device__ __forceinline__ uint32_t pack_bf16x2(float lo_val, float hi_val) {
    __nv_bfloat162 t = __halves2bfloat162(__float2bfloat16_rn(lo_val),
                                          __float2bfloat16_rn(hi_val));
    return *reinterpret_cast<uint32_t*>(&t);
}

// ---------------- CSR build ----------------
__global__ void zero_int(int* p, int n) {
    int i = blockIdx.x * blockDim.x + threadIdx.x;
    if (i < n) p[i] = 0;
}
__global__ void hist_kernel(const int* __restrict__ dst, int* __restrict__ cnt) {
    int e = blockIdx.x * blockDim.x + threadIdx.x;
    if (e < N_EDGES) atomicAdd(&cnt[dst[e]], 1);
}
__global__ void scan1_kernel(const int* __restrict__ cnt, int* __restrict__ excl,
                             int* __restrict__ blksum) {
    __shared__ int sh[SCAN_BLK];
    int tid = threadIdx.x;
    int i = blockIdx.x * SCAN_BLK + tid;
    int v = (i < N_NODES) ? cnt[i] : 0;
    sh[tid] = v;
    __syncthreads();
#pragma unroll
    for (int off = 1; off < SCAN_BLK; off <<= 1) {
        int t = (tid >= off) ? sh[tid - off] : 0;
        __syncthreads();
        sh[tid] += t;
        __syncthreads();
    }
    if (i <= N_NODES) excl[i] = sh[tid] - v;
    if (tid == SCAN_BLK - 1) blksum[blockIdx.x] = sh[tid];
}
__global__ void scan2_kernel(int* __restrict__ blksum) {
    __shared__ int sh[N_SCAN_BLKS];
    int tid = threadIdx.x;
    if (tid < N_SCAN_BLKS) sh[tid] = blksum[tid];
    __syncthreads();
    if (tid == 0) {
        int run = 0;
        for (int b = 0; b < N_SCAN_BLKS; b++) {
            int t = sh[b];
            sh[b] = run;
            run += t;
        }
    }
    __syncthreads();
    if (tid < N_SCAN_BLKS) blksum[tid] = sh[tid];
}
__global__ void scan3_kernel(int* __restrict__ excl, const int* __restrict__ blksum,
                             int* __restrict__ cur) {
    int i = blockIdx.x * blockDim.x + threadIdx.x;
    if (i < N_NODES) {
        int v = excl[i] + blksum[i / SCAN_BLK];
        excl[i] = v;
        cur[i] = v;
    }
    if (i == 0) excl[N_NODES] = N_EDGES;
}
__global__ void fill_kernel(const int* __restrict__ src, const int* __restrict__ dst,
                            int* __restrict__ cur, int* __restrict__ esrc) {
    int e = blockIdx.x * blockDim.x + threadIdx.x;
    if (e < N_EDGES) {
        int pos = atomicAdd(&cur[dst[e]], 1);
        esrc[pos] = src[e];
    }
}

// ---------------- streaming fp32 -> bf16 shadow (input_nodes is identity) ----------------
__global__ void cvt_kernel(const float* __restrict__ x,
                           __nv_bfloat16* __restrict__ xb, int n4) {
    int i = blockIdx.x * blockDim.x + threadIdx.x;
    if (i < n4) {
        float4 v = reinterpret_cast<const float4*>(x)[i];
        uint2 b;
        b.x = pack_bf16x2(v.x, v.y);
        b.y = pack_bf16x2(v.z, v.w);
        reinterpret_cast<uint2*>(xb)[i] = b;
    }
}

// ---------------- CSR mean aggregation: shfl-broadcast indices, burst gathers ----------------
// Warp per node. Lanes cooperatively load <=32 neighbor indices with ONE coalesced
// LDG, broadcast via shfl (no memory dep), then issue gathers in unroll-8 bursts
// (MLP >= 8). fp32 accumulate; mean written fp32.
__global__ void agg_kernel(const __nv_bfloat16* __restrict__ hb,
                           const int* __restrict__ esrc,
                           const int* __restrict__ off,
                           float* __restrict__ mean) {
    int t = blockIdx.x * blockDim.x + threadIdx.x;
    int v = t >> 5, l = t & 31;
    if (v >= N_NODES) return;
    int beg = off[v];
    int end = off[v + 1];
    const uint2* hb2 = reinterpret_cast<const uint2*>(hb);
    float ax = 0.f, ay = 0.f, az = 0.f, aw = 0.f;

    for (int base = beg; base < end; base += 32) {
        int n = end - base;
        if (n > 32) n = 32;
        int idx = (l < n) ? esrc[base + l] : 0;   // one coalesced LDG for the slab
        int j = 0;
        for (; j + 8 <= n; j += 8) {
            uint2 d[8];
#pragma unroll
            for (int q = 0; q < 8; q++) {
                int s = __shfl_sync(0xffffffffu, idx, j + q);
                d[q] = hb2[(size_t)s * 32 + l];
            }
#pragma unroll
            for (int q = 0; q < 8; q++) {
                float2 fa = __bfloat1622float2(*reinterpret_cast<__nv_bfloat162*>(&d[q].x));
                float2 fb = __bfloat1622float2(*reinterpret_cast<__nv_bfloat162*>(&d[q].y));
                ax += fa.x; ay += fa.y; az += fb.x; aw += fb.y;
            }
        }
        for (; j < n; j++) {
            int s = __shfl_sync(0xffffffffu, idx, j);
            uint2 d = hb2[(size_t)s * 32 + l];
            float2 fa = __bfloat1622float2(*reinterpret_cast<__nv_bfloat162*>(&d.x));
            float2 fb = __bfloat1622float2(*reinterpret_cast<__nv_bfloat162*>(&d.y));
            ax += fa.x; ay += fa.y; az += fb.x; aw += fb.y;
        }
    }
    float invd = 1.0f / fmaxf((float)(end - beg), 1.0f);
    reinterpret_cast<float4*>(mean)[v * 32 + l] =
        make_float4(ax * invd, ay * invd, az * invd, aw * invd);
}

// ---------------- mma.sync dual GEMM (bf16 hi/lo split -> fp32 accuracy) ----------------
// out[v,:] = mean[v] @ Wn + h[v] @ Ws + b  (optional ReLU). WB: also write bf16 shadow.
template <int BN, int NOUT, bool RELU, bool WB>
__global__ void __launch_bounds__(256) gemm_mma(
    const float* __restrict__ h, const float* __restrict__ mean,
    const float* __restrict__ Wn, const float* __restrict__ Ws,
    const float* __restrict__ bias, float* __restrict__ out,
    __nv_bfloat16* __restrict__ outb) {
    extern __shared__ char smem[];
    const uint32_t sb = smem_u32(smem);
    const int tid = threadIdx.x;
    const int wid = tid >> 5;
    const int lane = tid & 31;
    const int wm = wid >> 1;        // 0..3 (32 rows each)
    const int wn = wid & 1;         // 0..1 (BN/2 cols each)
    const int r0 = blockIdx.x * 128;

    constexpr int HN = BN / 2;
    constexpr int NT = HN / 8;
    constexpr uint32_t A_HI = 1024;
    constexpr uint32_t A_LO = 1024 + 16384;
    constexpr uint32_t B_HI = 1024 + 32768;
    constexpr uint32_t B_LO = B_HI + (uint32_t)BN * 128;

    if (tid < NOUT) *reinterpret_cast<float*>(smem + tid * 4) = bias[tid];

    const float4* mean4 = reinterpret_cast<const float4*>(mean);
    const float4* h4 = reinterpret_cast<const float4*>(h);

    float acc[2][NT][4];
#pragma unroll
    for (int i = 0; i < 2; i++)
#pragma unroll
        for (int j = 0; j < NT; j++)
#pragma unroll
            for (int q = 0; q < 4; q++) acc[i][j][q] = 0.f;

    for (int c = 0; c < 4; c++) {
        __syncthreads();

        // ---- A chunk: 128 rows x 64 floats -> bf16 hi/lo ----
#pragma unroll
        for (int it = 0; it < 8; it++) {
            int idx = tid + it * 256;
            int m = idx >> 4;
            int q = idx & 15;
            int row = r0 + m;
            float4 v = make_float4(0.f, 0.f, 0.f, 0.f);
            if (row < N_NODES)
                v = (c < 2) ? mean4[row * 32 + c * 16 + q]
                            : h4[row * 32 + (c - 2) * 16 + q];
            __nv_bfloat16 h0b, h1b, h2b, h3b, l0b, l1b, l2b, l3b;
            split_bf(v.x, h0b, l0b);
            split_bf(v.y, h1b, l1b);
            split_bf(v.z, h2b, l2b);
            split_bf(v.w, h3b, l3b);
            uint32_t off = (uint32_t)(m * 128 + q * 8);
            off ^= (uint32_t)(m & 7) << 4;
            __nv_bfloat162 hh0 = __halves2bfloat162(h0b, h1b);
            __nv_bfloat162 hh1 = __halves2bfloat162(h2b, h3b);
            __nv_bfloat162 ll0 = __halves2bfloat162(l0b, l1b);
            __nv_bfloat162 ll1 = __halves2bfloat162(l2b, l3b);
            *reinterpret_cast<uint2*>(smem + A_HI + off) =
                make_uint2(*reinterpret_cast<uint32_t*>(&hh0), *reinterpret_cast<uint32_t*>(&hh1));
            *reinterpret_cast<uint2*>(smem + A_LO + off) =
                make_uint2(*reinterpret_cast<uint32_t*>(&ll0), *reinterpret_cast<uint32_t*>(&ll1));
        }

        // ---- B chunk: 64 k-rows x BN cols of W ----
        {
            const float* W = (c < 2) ? Wn : Ws;
            int kb = (c & 1) * 64;
            if (BN == 128 && NOUT == 128) {
                const float4* W4 = reinterpret_cast<const float4*>(W);
#pragma unroll
                for (int it = 0; it < 8; it++) {
                    int idx = tid + it * 256;
                    int k = idx >> 5;
                    int nq = idx & 31;
                    float4 v = W4[(kb + k) * 32 + nq];
                    __nv_bfloat16 h0b, h1b, h2b, h3b, l0b, l1b, l2b, l3b;
                    split_bf(v.x, h0b, l0b);
                    split_bf(v.y, h1b, l1b);
                    split_bf(v.z, h2b, l2b);
                    split_bf(v.w, h3b, l3b);
                    uint32_t off = (uint32_t)(k * 256 + nq * 8);
                    off ^= (uint32_t)(k & 7) << 4;
                    __nv_bfloat162 hh0 = __halves2bfloat162(h0b, h1b);
                    __nv_bfloat162 hh1 = __halves2bfloat162(h2b, h3b);
                    __nv_bfloat162 ll0 = __halves2bfloat162(l0b, l1b);
                    __nv_bfloat162 ll1 = __halves2bfloat162(l2b, l3b);
                    *reinterpret_cast<uint2*>(smem + B_HI + off) =
                        make_uint2(*reinterpret_cast<uint32_t*>(&hh0), *reinterpret_cast<uint32_t*>(&hh1));
                    *reinterpret_cast<uint2*>(smem + B_LO + off) =
                        make_uint2(*reinterpret_cast<uint32_t*>(&ll0), *reinterpret_cast<uint32_t*>(&ll1));
                }
            } else {
#pragma unroll
                for (int it = 0; it < BN * 64 / 256; it++) {
                    int idx = tid + it * 256;
                    int k = idx / BN;
                    int n = idx % BN;
                    float w = (n < NOUT) ? W[(kb + k) * NOUT + n] : 0.f;
                    __nv_bfloat16 hi, lo;
                    split_bf(w, hi, lo);
                    uint32_t off = (uint32_t)(k * BN * 2 + n * 2);
                    off ^= (uint32_t)(k & 7) << 4;
                    *reinterpret_cast<__nv_bfloat16*>(smem + B_HI + off) = hi;
                    *reinterpret_cast<__nv_bfloat16*>(smem + B_LO + off) = lo;
                }
            }
        }
        __syncthreads();

        // ---- compute: 4 k-steps of 16 ----
#pragma unroll
        for (int kt = 0; kt < 4; kt++) {
            uint32_t ah[2][4], al[2][4];
            int arow_base = wm * 32 + (lane & 15);
            int akb = kt * 32 + ((lane >> 4) << 4);
#pragma unroll
            for (int mt = 0; mt < 2; mt++) {
                int row = arow_base + mt * 16;
                uint32_t off = (uint32_t)(row * 128 + akb);
                off ^= (uint32_t)(row & 7) << 4;
                ldsm4(ah[mt], sb + A_HI + off);
                ldsm4(al[mt], sb + A_LO + off);
            }
            int bk = kt * 16 + (lane & 15);
#pragma unroll
            for (int np = 0; np < NT / 2; np++) {
                int n0 = wn * HN + np * 16 + ((lane >> 4) << 3);
                uint32_t off = (uint32_t)(bk * BN * 2 + n0 * 2);
                off ^= (uint32_t)(bk & 7) << 4;
                uint32_t bh[4], bl[4];
                ldsm4t(bh, sb + B_HI + off);
                ldsm4t(bl, sb + B_LO + off);
#pragma unroll
                for (int hh = 0; hh < 2; hh++) {
                    int nt = np * 2 + hh;
#pragma unroll
                    for (int mt = 0; mt < 2; mt++) {
                        mma_bf16(acc[mt][nt], ah[mt], bh + 2 * hh);
                        mma_bf16(acc[mt][nt], ah[mt], bl + 2 * hh);
                        mma_bf16(acc[mt][nt], al[mt], bh + 2 * hh);
                    }
                }
            }
        }
    }

    // ---- epilogue ----
    const float* biasS = reinterpret_cast<const float*>(smem);
#pragma unroll
    for (int mt = 0; mt < 2; mt++) {
        int row = r0 + wm * 32 + mt * 16 + (lane >> 2);
#pragma unroll
        for (int nt = 0; nt < NT; nt++) {
            int col = wn * HN + nt * 8 + (lane & 3) * 2;
#pragma unroll
            for (int p = 0; p < 2; p++) {
                int r = row + p * 8;
                if (r < N_NODES) {
                    float v0 = acc[mt][nt][2 * p + 0];
                    float v1 = acc[mt][nt][2 * p + 1];
                    if (WB) {
                        float w0 = v0 + biasS[col];
                        float w1 = v1 + biasS[col + 1];
                        if (RELU) { w0 = fmaxf(w0, 0.f); w1 = fmaxf(w1, 0.f); }
                        reinterpret_cast<float2*>(out)[((size_t)r * NOUT + col) >> 1] =
                            make_float2(w0, w1);
                        reinterpret_cast<uint32_t*>(outb)[((size_t)r * NOUT + col) >> 1] =
                            pack_bf16x2(w0, w1);
                    } else {
                        if (col < NOUT) {
                            float v = v0 + biasS[col];
                            if (RELU) v = fmaxf(v, 0.f);
                            out[(size_t)r * NOUT + col] = v;
                        }
                        if (col + 1 < NOUT) {
                            float v = v1 + biasS[col + 1];
                            if (RELU) v = fmaxf(v, 0.f);
                            out[(size_t)r * NOUT + col + 1] = v;
                        }
                    }
                }
            }
        }
    }
}

// ---------------- launch ----------------
extern "C" void kernel_launch(void* const* d_in, const int* in_sizes, int n_in,
                              void* d_out, int out_size) {
    const float* embed  = (const float*)d_in[0];
    const float* Wself0 = (const float*)d_in[1];
    const float* Wneigh0= (const float*)d_in[2];
    const float* b0     = (const float*)d_in[3];
    const float* Wself1 = (const float*)d_in[4];
    const float* Wneigh1= (const float*)d_in[5];
    const float* b1     = (const float*)d_in[6];
    const float* Wself2 = (const float*)d_in[7];
    const float* Wneigh2= (const float*)d_in[8];
    const float* b2     = (const float*)d_in[9];
    const int* src      = (const int*)d_in[11];
    const int* dst      = (const int*)d_in[12];
    float* out = (float*)d_out;

    float *h0, *h1, *mean;
    __nv_bfloat16 *hb0, *hb1;
    int *cnt, *off, *cur, *esrc, *blksum;
    cudaGetSymbolAddress((void**)&h0, g_h0);
    cudaGetSymbolAddress((void**)&h1, g_h1);
    cudaGetSymbolAddress((void**)&mean, g_mean);
    cudaGetSymbolAddress((void**)&hb0, g_hb0);
    cudaGetSymbolAddress((void**)&hb1, g_hb1);
    cudaGetSymbolAddress((void**)&cnt, g_cnt);
    cudaGetSymbolAddress((void**)&off, g_off);
    cudaGetSymbolAddress((void**)&cur, g_cur);
    cudaGetSymbolAddress((void**)&esrc, g_esrc);
    cudaGetSymbolAddress((void**)&blksum, g_blksum);

    const int T = 256;
    const int gemm_blocks = (N_NODES + 127) / 128;           // 782
    const int warp_blocks = (N_NODES * 32 + T - 1) / T;
    const int nf4 = N_NODES * 32;

    const int SMEM_128 = 1024 + 32768 + 2 * 128 * 128;       // 66560
    const int SMEM_64  = 1024 + 32768 + 2 * 64 * 128;        // 50176
    cudaFuncSetAttribute(gemm_mma<128, 128, true, true>,
                         cudaFuncAttributeMaxDynamicSharedMemorySize, SMEM_128);
    cudaFuncSetAttribute(gemm_mma<64, NCLS, false, false>,
                         cudaFuncAttributeMaxDynamicSharedMemorySize, SMEM_64);

    // ---- CSR build (once; reused by all 3 layers) ----
    zero_int<<<(N_NODES + T - 1) / T, T>>>(cnt, N_NODES);
    hist_kernel<<<(N_EDGES + T - 1) / T, T>>>(dst, cnt);
    scan1_kernel<<<N_SCAN_BLKS, SCAN_BLK>>>(cnt, off, blksum);
    scan2_kernel<<<1, 128>>>(blksum);
    scan3_kernel<<<(N_NODES + T - 1) / T, T>>>(off, blksum, cur);
    fill_kernel<<<(N_EDGES + T - 1) / T, T>>>(src, dst, cur, esrc);

    // ---- bf16 shadow of embeddings (input_nodes is arange -> h0 == embed) ----
    cvt_kernel<<<(nf4 + T - 1) / T, T>>>(embed, hb0, nf4);

    // layer 0: embed -> h1 (relu)
    agg_kernel<<<warp_blocks, T>>>(hb0, esrc, off, mean);
    gemm_mma<128, 128, true, true><<<gemm_blocks, T, SMEM_128>>>(
        embed, mean, Wneigh0, Wself0, b0, h1, hb1);

    // layer 1: h1 -> h0 (relu)
    agg_kernel<<<warp_blocks, T>>>(hb1, esrc, off, mean);
    gemm_mma<128, 128, true, true><<<gemm_blocks, T, SMEM_128>>>(
        h1, mean, Wneigh1, Wself1, b1, h0, hb0);

    // layer 2: h0 -> out (no relu, 47 classes)
    agg_kernel<<<warp_blocks, T>>>(hb0, esrc, off, mean);
    gemm_mma<64, NCLS, false, false><<<gemm_blocks, T, SMEM_64>>>(
        h0, mean, Wneigh2, Wself2, b2, out, nullptr);
}

// round 8
// speedup vs baseline: 1.0590x; 1.0590x over previous
#include <cuda_runtime.h>
#include <cuda_bf16.h>
#include <cstdint>

#define N_NODES 100000
#define N_EDGES 1600000
#define FEAT 128
#define NCLS 47
#define SCAN_BLK 1024
#define N_SCAN_BLKS ((N_NODES + SCAN_BLK - 1) / SCAN_BLK)   // 98

// ---------------- scratch (no allocation allowed) ----------------
__device__ __align__(16) float g_h0[N_NODES * FEAT];
__device__ __align__(16) float g_h1[N_NODES * FEAT];
__device__ __align__(16) float g_mean[N_NODES * FEAT];
__device__ __align__(16) __nv_bfloat16 g_hb0[N_NODES * FEAT];
__device__ __align__(16) __nv_bfloat16 g_hb1[N_NODES * FEAT];
__device__ __align__(16) int   g_cnt[N_NODES];
__device__ __align__(16) int   g_off[N_NODES + 1];
__device__ __align__(16) int   g_cur[N_NODES];
__device__ __align__(16) int   g_esrc[N_EDGES];
__device__ __align__(16) int   g_blksum[N_SCAN_BLKS];

// ---------------- PTX helpers ----------------
__device__ __forceinline__ uint32_t smem_u32(const void* p) {
    uint32_t a;
    asm("{ .reg .u64 t; cvta.to.shared.u64 t, %1; cvt.u32.u64 %0, t; }"
        : "=r"(a) : "l"(p));
    return a;
}
__device__ __forceinline__ void ldsm4(uint32_t* r, uint32_t a) {
    asm volatile("ldmatrix.sync.aligned.m8n8.x4.shared.b16 {%0,%1,%2,%3}, [%4];"
                 : "=r"(r[0]), "=r"(r[1]), "=r"(r[2]), "=r"(r[3]) : "r"(a));
}
__device__ __forceinline__ void ldsm4t(uint32_t* r, uint32_t a) {
    asm volatile("ldmatrix.sync.aligned.m8n8.x4.trans.shared.b16 {%0,%1,%2,%3}, [%4];"
                 : "=r"(r[0]), "=r"(r[1]), "=r"(r[2]), "=r"(r[3]) : "r"(a));
}
__device__ __forceinline__ void mma_bf16(float* d, const uint32_t* a, const uint32_t* b) {
    asm volatile(
        "mma.sync.aligned.m16n8k16.row.col.f32.bf16.bf16.f32 "
        "{%0,%1,%2,%3}, {%4,%5,%6,%7}, {%8,%9}, {%0,%1,%2,%3};"
        : "+f"(d[0]), "+f"(d[1]), "+f"(d[2]), "+f"(d[3])
        : "r"(a[0]), "r"(a[1]), "r"(a[2]), "r"(a[3]), "r"(b[0]), "r"(b[1]));
}
__device__ __forceinline__ void split_bf(float x, __nv_bfloat16& hi, __nv_bfloat16& lo) {
    hi = __float2bfloat16_rn(x);
    lo = __float2bfloat16_rn(x - __bfloat162float(hi));
}
__device__ __forceinline__ uint32_t pack_bf16x2(float lo_val, float hi_val) {
    __nv_bfloat162 t = __halves2bfloat162(__float2bfloat16_rn(lo_val),
                                          __float2bfloat16_rn(hi_val));
    return *reinterpret_cast<uint32_t*>(&t);
}

// ---------------- prep: zero cnt + bf16 shadow of embeddings ----------------
__global__ void prep_kernel(const float* __restrict__ embed,
                            __nv_bfloat16* __restrict__ hb0,
                            int* __restrict__ cnt, int n4) {
    int i = blockIdx.x * blockDim.x + threadIdx.x;
    if (i < n4) {
        float4 v = reinterpret_cast<const float4*>(embed)[i];
        uint2 b;
        b.x = pack_bf16x2(v.x, v.y);
        b.y = pack_bf16x2(v.z, v.w);
        reinterpret_cast<uint2*>(hb0)[i] = b;
    }
    if (i < N_NODES) cnt[i] = 0;
}

// ---------------- CSR build ----------------
__global__ void hist_kernel(const int* __restrict__ dst, int* __restrict__ cnt) {
    int e = blockIdx.x * blockDim.x + threadIdx.x;
    if (e < N_EDGES) atomicAdd(&cnt[dst[e]], 1);
}
__global__ void scan1_kernel(const int* __restrict__ cnt, int* __restrict__ excl,
                             int* __restrict__ blksum) {
    __shared__ int sh[SCAN_BLK];
    int tid = threadIdx.x;
    int i = blockIdx.x * SCAN_BLK + tid;
    int v = (i < N_NODES) ? cnt[i] : 0;
    sh[tid] = v;
    __syncthreads();
#pragma unroll
    for (int off = 1; off < SCAN_BLK; off <<= 1) {
        int t = (tid >= off) ? sh[tid - off] : 0;
        __syncthreads();
        sh[tid] += t;
        __syncthreads();
    }
    if (i <= N_NODES) excl[i] = sh[tid] - v;
    if (tid == SCAN_BLK - 1) blksum[blockIdx.x] = sh[tid];
}
// scan3 with fused block-sum scan: every block redundantly scans the 98 sums.
__global__ void scan3_kernel(int* __restrict__ excl, const int* __restrict__ blksum,
                             int* __restrict__ cur) {
    __shared__ int sh[N_SCAN_BLKS];
    int tid = threadIdx.x;
    if (tid < N_SCAN_BLKS) sh[tid] = blksum[tid];
    __syncthreads();
    if (tid == 0) {
        int run = 0;
        for (int b = 0; b < N_SCAN_BLKS; b++) {
            int t = sh[b];
            sh[b] = run;
            run += t;
        }
    }
    __syncthreads();
    int i = blockIdx.x * blockDim.x + tid;
    if (i < N_NODES) {
        int v = excl[i] + sh[i / SCAN_BLK];
        excl[i] = v;
        cur[i] = v;
    }
    if (i == 0) excl[N_NODES] = N_EDGES;
}
__global__ void fill_kernel(const int* __restrict__ src, const int* __restrict__ dst,
                            int* __restrict__ cur, int* __restrict__ esrc) {
    int e = blockIdx.x * blockDim.x + threadIdx.x;
    if (e < N_EDGES) {
        int pos = atomicAdd(&cur[dst[e]], 1);
        esrc[pos] = src[e];
    }
}

// ---------------- CSR mean aggregation: bf16 gather, fp32 accumulate (R6 style) ----------------
__global__ void agg_kernel(const __nv_bfloat16* __restrict__ hb,
                           const int* __restrict__ esrc,
                           const int* __restrict__ off,
                           float* __restrict__ mean) {
    int t = blockIdx.x * blockDim.x + threadIdx.x;
    int v = t >> 5, l = t & 31;
    if (v >= N_NODES) return;
    int beg = off[v];
    int end = off[v + 1];
    const uint2* hb2 = reinterpret_cast<const uint2*>(hb);
    float ax = 0.f, ay = 0.f, az = 0.f, aw = 0.f;
    int j = beg;
    for (; j + 4 <= end; j += 4) {
        int s0 = esrc[j], s1 = esrc[j + 1], s2 = esrc[j + 2], s3 = esrc[j + 3];
        uint2 d0 = hb2[s0 * 32 + l];
        uint2 d1 = hb2[s1 * 32 + l];
        uint2 d2 = hb2[s2 * 32 + l];
        uint2 d3 = hb2[s3 * 32 + l];
        float2 f0a = __bfloat1622float2(*reinterpret_cast<__nv_bfloat162*>(&d0.x));
        float2 f0b = __bfloat1622float2(*reinterpret_cast<__nv_bfloat162*>(&d0.y));
        float2 f1a = __bfloat1622float2(*reinterpret_cast<__nv_bfloat162*>(&d1.x));
        float2 f1b = __bfloat1622float2(*reinterpret_cast<__nv_bfloat162*>(&d1.y));
        float2 f2a = __bfloat1622float2(*reinterpret_cast<__nv_bfloat162*>(&d2.x));
        float2 f2b = __bfloat1622float2(*reinterpret_cast<__nv_bfloat162*>(&d2.y));
        float2 f3a = __bfloat1622float2(*reinterpret_cast<__nv_bfloat162*>(&d3.x));
        float2 f3b = __bfloat1622float2(*reinterpret_cast<__nv_bfloat162*>(&d3.y));
        ax += (f0a.x + f1a.x) + (f2a.x + f3a.x);
        ay += (f0a.y + f1a.y) + (f2a.y + f3a.y);
        az += (f0b.x + f1b.x) + (f2b.x + f3b.x);
        aw += (f0b.y + f1b.y) + (f2b.y + f3b.y);
    }
    for (; j < end; j++) {
        uint2 d = hb2[esrc[j] * 32 + l];
        float2 fa = __bfloat1622float2(*reinterpret_cast<__nv_bfloat162*>(&d.x));
        float2 fb = __bfloat1622float2(*reinterpret_cast<__nv_bfloat162*>(&d.y));
        ax += fa.x; ay += fa.y; az += fb.x; aw += fb.y;
    }
    float invd = 1.0f / fmaxf((float)(end - beg), 1.0f);
    reinterpret_cast<float4*>(mean)[v * 32 + l] =
        make_float4(ax * invd, ay * invd, az * invd, aw * invd);
}

// ---------------- mma.sync dual GEMM (bf16 hi/lo split -> fp32 accuracy) ----------------
// out[v,:] = mean[v] @ Wn + h[v] @ Ws + b  (optional ReLU). WB: also write bf16 shadow.
// Epilogue staged through SMEM for fully-coalesced global writes.
template <int BN, int NOUT, bool RELU, bool WB>
__global__ void __launch_bounds__(256) gemm_mma(
    const float* __restrict__ h, const float* __restrict__ mean,
    const float* __restrict__ Wn, const float* __restrict__ Ws,
    const float* __restrict__ bias, float* __restrict__ out,
    __nv_bfloat16* __restrict__ outb) {
    extern __shared__ char smem[];
    const uint32_t sb = smem_u32(smem);
    const int tid = threadIdx.x;
    const int wid = tid >> 5;
    const int lane = tid & 31;
    const int wm = wid >> 1;        // 0..3 (32 rows each)
    const int wn = wid & 1;         // 0..1 (BN/2 cols each)
    const int r0 = blockIdx.x * 128;

    constexpr int HN = BN / 2;
    constexpr int NT = HN / 8;
    constexpr uint32_t A_HI = 1024;
    constexpr uint32_t A_LO = 1024 + 16384;
    constexpr uint32_t B_HI = 1024 + 32768;
    constexpr uint32_t B_LO = B_HI + (uint32_t)BN * 128;

    if (tid < NOUT) *reinterpret_cast<float*>(smem + tid * 4) = bias[tid];

    const float4* mean4 = reinterpret_cast<const float4*>(mean);
    const float4* h4 = reinterpret_cast<const float4*>(h);

    float acc[2][NT][4];
#pragma unroll
    for (int i = 0; i < 2; i++)
#pragma unroll
        for (int j = 0; j < NT; j++)
#pragma unroll
            for (int q = 0; q < 4; q++) acc[i][j][q] = 0.f;

    for (int c = 0; c < 4; c++) {
        __syncthreads();

        // ---- A chunk: 128 rows x 64 floats -> bf16 hi/lo ----
#pragma unroll
        for (int it = 0; it < 8; it++) {
            int idx = tid + it * 256;
            int m = idx >> 4;
            int q = idx & 15;
            int row = r0 + m;
            float4 v = make_float4(0.f, 0.f, 0.f, 0.f);
            if (row < N_NODES)
                v = (c < 2) ? mean4[row * 32 + c * 16 + q]
                            : h4[row * 32 + (c - 2) * 16 + q];
            __nv_bfloat16 h0b, h1b, h2b, h3b, l0b, l1b, l2b, l3b;
            split_bf(v.x, h0b, l0b);
            split_bf(v.y, h1b, l1b);
            split_bf(v.z, h2b, l2b);
            split_bf(v.w, h3b, l3b);
            uint32_t off = (uint32_t)(m * 128 + q * 8);
            off ^= (uint32_t)(m & 7) << 4;
            __nv_bfloat162 hh0 = __halves2bfloat162(h0b, h1b);
            __nv_bfloat162 hh1 = __halves2bfloat162(h2b, h3b);
            __nv_bfloat162 ll0 = __halves2bfloat162(l0b, l1b);
            __nv_bfloat162 ll1 = __halves2bfloat162(l2b, l3b);
            *reinterpret_cast<uint2*>(smem + A_HI + off) =
                make_uint2(*reinterpret_cast<uint32_t*>(&hh0), *reinterpret_cast<uint32_t*>(&hh1));
            *reinterpret_cast<uint2*>(smem + A_LO + off) =
                make_uint2(*reinterpret_cast<uint32_t*>(&ll0), *reinterpret_cast<uint32_t*>(&ll1));
        }

        // ---- B chunk: 64 k-rows x BN cols of W ----
        {
            const float* W = (c < 2) ? Wn : Ws;
            int kb = (c & 1) * 64;
            if (BN == 128 && NOUT == 128) {
                const float4* W4 = reinterpret_cast<const float4*>(W);
#pragma unroll
                for (int it = 0; it < 8; it++) {
                    int idx = tid + it * 256;
                    int k = idx >> 5;
                    int nq = idx & 31;
                    float4 v = W4[(kb + k) * 32 + nq];
                    __nv_bfloat16 h0b, h1b, h2b, h3b, l0b, l1b, l2b, l3b;
                    split_bf(v.x, h0b, l0b);
                    split_bf(v.y, h1b, l1b);
                    split_bf(v.z, h2b, l2b);
                    split_bf(v.w, h3b, l3b);
                    uint32_t off = (uint32_t)(k * 256 + nq * 8);
                    off ^= (uint32_t)(k & 7) << 4;
                    __nv_bfloat162 hh0 = __halves2bfloat162(h0b, h1b);
                    __nv_bfloat162 hh1 = __halves2bfloat162(h2b, h3b);
                    __nv_bfloat162 ll0 = __halves2bfloat162(l0b, l1b);
                    __nv_bfloat162 ll1 = __halves2bfloat162(l2b, l3b);
                    *reinterpret_cast<uint2*>(smem + B_HI + off) =
                        make_uint2(*reinterpret_cast<uint32_t*>(&hh0), *reinterpret_cast<uint32_t*>(&hh1));
                    *reinterpret_cast<uint2*>(smem + B_LO + off) =
                        make_uint2(*reinterpret_cast<uint32_t*>(&ll0), *reinterpret_cast<uint32_t*>(&ll1));
                }
            } else {
#pragma unroll
                for (int it = 0; it < BN * 64 / 256; it++) {
                    int idx = tid + it * 256;
                    int k = idx / BN;
                    int n = idx % BN;
                    float w = (n < NOUT) ? W[(kb + k) * NOUT + n] : 0.f;
                    __nv_bfloat16 hi, lo;
                    split_bf(w, hi, lo);
                    uint32_t off = (uint32_t)(k * BN * 2 + n * 2);
                    off ^= (uint32_t)(k & 7) << 4;
                    *reinterpret_cast<__nv_bfloat16*>(smem + B_HI + off) = hi;
                    *reinterpret_cast<__nv_bfloat16*>(smem + B_LO + off) = lo;
                }
            }
        }
        __syncthreads();

        // ---- compute: 4 k-steps of 16 ----
#pragma unroll
        for (int kt = 0; kt < 4; kt++) {
            uint32_t ah[2][4], al[2][4];
            int arow_base = wm * 32 + (lane & 15);
            int akb = kt * 32 + ((lane >> 4) << 4);
#pragma unroll
            for (int mt = 0; mt < 2; mt++) {
                int row = arow_base + mt * 16;
                uint32_t off = (uint32_t)(row * 128 + akb);
                off ^= (uint32_t)(row & 7) << 4;
                ldsm4(ah[mt], sb + A_HI + off);
                ldsm4(al[mt], sb + A_LO + off);
            }
            int bk = kt * 16 + (lane & 15);
#pragma unroll
            for (int np = 0; np < NT / 2; np++) {
                int n0 = wn * HN + np * 16 + ((lane >> 4) << 3);
                uint32_t off = (uint32_t)(bk * BN * 2 + n0 * 2);
                off ^= (uint32_t)(bk & 7) << 4;
                uint32_t bh[4], bl[4];
                ldsm4t(bh, sb + B_HI + off);
                ldsm4t(bl, sb + B_LO + off);
#pragma unroll
                for (int hh = 0; hh < 2; hh++) {
                    int nt = np * 2 + hh;
#pragma unroll
                    for (int mt = 0; mt < 2; mt++) {
                        mma_bf16(acc[mt][nt], ah[mt], bh + 2 * hh);
                        mma_bf16(acc[mt][nt], ah[mt], bl + 2 * hh);
                        mma_bf16(acc[mt][nt], al[mt], bh + 2 * hh);
                    }
                }
            }
        }
    }

    // ---- epilogue: stage through SMEM for coalesced global writes ----
    const float* biasS = reinterpret_cast<const float*>(smem);
    __syncthreads();   // A/B tiles no longer needed; reuse region as D staging
    float* D = reinterpret_cast<float*>(smem + 1024);

    if (BN == 128) {
        // swizzled layout: word index = r*128 + (col ^ ((r&7)<<3)), fits 64KB exactly
#pragma unroll
        for (int mt = 0; mt < 2; mt++) {
#pragma unroll
            for (int nt = 0; nt < NT; nt++) {
                int col = wn * HN + nt * 8 + (lane & 3) * 2;
#pragma unroll
                for (int p = 0; p < 2; p++) {
                    int rl = wm * 32 + mt * 16 + (lane >> 2) + p * 8;
                    float w0 = acc[mt][nt][2 * p + 0] + biasS[col];
                    float w1 = acc[mt][nt][2 * p + 1] + biasS[col + 1];
                    if (RELU) { w0 = fmaxf(w0, 0.f); w1 = fmaxf(w1, 0.f); }
                    int cs = col ^ ((rl & 7) << 3);
                    *reinterpret_cast<float2*>(&D[rl * 128 + cs]) = make_float2(w0, w1);
                }
            }
        }
        __syncthreads();
        // coalesced writeout: each thread copies float4s
#pragma unroll
        for (int it = 0; it < 16; it++) {
            int idx = tid + it * 256;
            int rl = idx >> 5;
            int q = idx & 31;
            int r = r0 + rl;
            if (r < N_NODES) {
                int cs = (q * 4) ^ ((rl & 7) << 3);
                float4 v = *reinterpret_cast<float4*>(&D[rl * 128 + cs]);
                reinterpret_cast<float4*>(out)[(size_t)r * 32 + q] = v;
                if (WB) {
                    uint2 b;
                    b.x = pack_bf16x2(v.x, v.y);
                    b.y = pack_bf16x2(v.z, v.w);
                    reinterpret_cast<uint2*>(outb)[(size_t)r * 32 + q] = b;
                }
            }
        }
    } else {
        // NOUT=47 path: stage with padded stride 66, flat coalesced writeout
        constexpr int STRIDE = 66;
#pragma unroll
        for (int mt = 0; mt < 2; mt++) {
#pragma unroll
            for (int nt = 0; nt < NT; nt++) {
                int col = wn * HN + nt * 8 + (lane & 3) * 2;
#pragma unroll
                for (int p = 0; p < 2; p++) {
                    int rl = wm * 32 + mt * 16 + (lane >> 2) + p * 8;
                    if (col < NOUT) {
                        float w0 = acc[mt][nt][2 * p + 0] + biasS[col];
                        if (RELU) w0 = fmaxf(w0, 0.f);
                        D[rl * STRIDE + col] = w0;
                    }
                    if (col + 1 < NOUT) {
                        float w1 = acc[mt][nt][2 * p + 1] + biasS[col + 1];
                        if (RELU) w1 = fmaxf(w1, 0.f);
                        D[rl * STRIDE + col + 1] = w1;
                    }
                }
            }
        }
        __syncthreads();
        int nrows = N_NODES - r0;
        if (nrows > 128) nrows = 128;
        int total = nrows * NOUT;
        for (int e = tid; e < total; e += 256) {
            int rl = e / NOUT;
            int cc = e - rl * NOUT;
            out[(size_t)(r0) * NOUT + e] = D[rl * STRIDE + cc];
        }
    }
}

// ---------------- launch ----------------
extern "C" void kernel_launch(void* const* d_in, const int* in_sizes, int n_in,
                              void* d_out, int out_size) {
    const float* embed  = (const float*)d_in[0];
    const float* Wself0 = (const float*)d_in[1];
    const float* Wneigh0= (const float*)d_in[2];
    const float* b0     = (const float*)d_in[3];
    const float* Wself1 = (const float*)d_in[4];
    const float* Wneigh1= (const float*)d_in[5];
    const float* b1     = (const float*)d_in[6];
    const float* Wself2 = (const float*)d_in[7];
    const float* Wneigh2= (const float*)d_in[8];
    const float* b2     = (const float*)d_in[9];
    const int* src      = (const int*)d_in[11];
    const int* dst      = (const int*)d_in[12];
    float* out = (float*)d_out;

    float *h0, *h1, *mean;
    __nv_bfloat16 *hb0, *hb1;
    int *cnt, *off, *cur, *esrc, *blksum;
    cudaGetSymbolAddress((void**)&h0, g_h0);
    cudaGetSymbolAddress((void**)&h1, g_h1);
    cudaGetSymbolAddress((void**)&mean, g_mean);
    cudaGetSymbolAddress((void**)&hb0, g_hb0);
    cudaGetSymbolAddress((void**)&hb1, g_hb1);
    cudaGetSymbolAddress((void**)&cnt, g_cnt);
    cudaGetSymbolAddress((void**)&off, g_off);
    cudaGetSymbolAddress((void**)&cur, g_cur);
    cudaGetSymbolAddress((void**)&esrc, g_esrc);
    cudaGetSymbolAddress((void**)&blksum, g_blksum);

    const int T = 256;
    const int gemm_blocks = (N_NODES + 127) / 128;           // 782
    const int warp_blocks = (N_NODES * 32 + T - 1) / T;
    const int nf4 = N_NODES * 32;

    const int SMEM_128 = 1024 + 32768 + 2 * 128 * 128;       // 66560 (D stage fits exactly)
    const int SMEM_64  = 1024 + 128 * 66 * 4;                // 34816 (>= B tiles 17408+... ok)
    const int SMEM_64_REAL = (SMEM_64 > (1024 + 32768 + 2 * 64 * 128))
                                 ? SMEM_64 : (1024 + 32768 + 2 * 64 * 128);
    cudaFuncSetAttribute(gemm_mma<128, 128, true, true>,
                         cudaFuncAttributeMaxDynamicSharedMemorySize, SMEM_128);
    cudaFuncSetAttribute(gemm_mma<64, NCLS, false, false>,
                         cudaFuncAttributeMaxDynamicSharedMemorySize, SMEM_64_REAL);

    // ---- prep (zero cnt + bf16 shadow of embeddings; input_nodes is arange) ----
    prep_kernel<<<(nf4 + T - 1) / T, T>>>(embed, hb0, cnt, nf4);

    // ---- CSR build ----
    hist_kernel<<<(N_EDGES + T - 1) / T, T>>>(dst, cnt);
    scan1_kernel<<<N_SCAN_BLKS, SCAN_BLK>>>(cnt, off, blksum);
    scan3_kernel<<<(N_NODES + SCAN_BLK - 1) / SCAN_BLK, SCAN_BLK>>>(off, blksum, cur);
    fill_kernel<<<(N_EDGES + T - 1) / T, T>>>(src, dst, cur, esrc);

    // layer 0: embed -> h1 (relu)
    agg_kernel<<<warp_blocks, T>>>(hb0, esrc, off, mean);
    gemm_mma<128, 128, true, true><<<gemm_blocks, T, SMEM_128>>>(
        embed, mean, Wneigh0, Wself0, b0, h1, hb1);

    // layer 1: h1 -> h0 (relu)
    agg_kernel<<<warp_blocks, T>>>(hb1, esrc, off, mean);
    gemm_mma<128, 128, true, true><<<gemm_blocks, T, SMEM_128>>>(
        h1, mean, Wneigh1, Wself1, b1, h0, hb0);

    // layer 2: h0 -> out (no relu, 47 classes)
    agg_kernel<<<warp_blocks, T>>>(hb0, esrc, off, mean);
    gemm_mma<64, NCLS, false, false><<<gemm_blocks, T, SMEM_64_REAL>>>(
        h0, mean, Wneigh2, Wself2, b2, out, nullptr);
}